// round 1
// baseline (speedup 1.0000x reference)
#include <cuda_runtime.h>
#include <cstdint>

// IndexAddInplace: out = x; out[idx[i]] += src[i]  (duplicates accumulate)
// x: [N_DST=100000, D=512] f32, idx: [N_SRC=200000] int64 (or int32, detected),
// src: [N_SRC, D] f32. HBM-bound: ~1.2 GB total traffic.

#define DVAL 512
#define DV   128   // D / 4 (float4 chunks per row)

__device__ int g_idx_is64;

// Detect idx element width without host sync (graph-capturable).
// Reads the first n_src int32 words — safe whether the buffer holds
// n_src int32s or n_src int64s. If int64 with values < 2^31, every odd
// 32-bit word is 0. If int32, odd words are random indices (virtually
// certain to contain a nonzero among 100000 samples).
__global__ void detect_idx_dtype_kernel(const int* __restrict__ idx32, int n_src) {
    __shared__ int s_nonzero_odd;
    if (threadIdx.x == 0) s_nonzero_odd = 0;
    __syncthreads();
    int local = 0;
    int half = n_src >> 1;
    for (int i = threadIdx.x; i < half; i += blockDim.x) {
        if (idx32[2 * i + 1] != 0) local = 1;
    }
    if (local) atomicOr(&s_nonzero_odd, 1);
    __syncthreads();
    if (threadIdx.x == 0) g_idx_is64 = s_nonzero_odd ? 0 : 1;
}

// out = x, vectorized float4 copy.
__global__ void copy_kernel(const float4* __restrict__ x, float4* __restrict__ out,
                            int n_vec) {
    int t = blockIdx.x * blockDim.x + threadIdx.x;
    if (t < n_vec) out[t] = x[t];
}

// Scatter-add src rows into out via vectorized reduction (red.global.add.v4.f32
// — fire-and-forget REDG, no return round-trip). One thread per float4 chunk;
// consecutive threads cover one src row -> fully coalesced src read, and the
// 128 threads of a row share one idx load (L1/L2 cached).
__global__ void scatter_add_kernel(const void* __restrict__ idx_raw,
                                   const float4* __restrict__ src,
                                   float* __restrict__ out,
                                   int total_vec) {
    int t = blockIdx.x * blockDim.x + threadIdx.x;
    if (t >= total_vec) return;
    int row = t >> 7;        // / DV
    int col = t & (DV - 1);  // % DV

    long long d;
    if (g_idx_is64) {
        d = ((const long long*)idx_raw)[row];
    } else {
        d = (long long)((const int*)idx_raw)[row];
    }

    float4 v = src[t];
    float* p = out + d * (long long)DVAL + (long long)col * 4;
    asm volatile("red.global.add.v4.f32 [%0], {%1, %2, %3, %4};"
                 :: "l"(p), "f"(v.x), "f"(v.y), "f"(v.z), "f"(v.w)
                 : "memory");
}

extern "C" void kernel_launch(void* const* d_in, const int* in_sizes, int n_in,
                              void* d_out, int out_size) {
    // Inputs per reference order: x [N_DST*D] f32, idx [N_SRC] int, src [N_SRC*D] f32
    const float* x   = (const float*)d_in[0];
    const void*  idx = (const void*)d_in[1];
    const float* src = (const float*)d_in[2];
    float* out = (float*)d_out;

    const int n_src = in_sizes[1];            // 200000
    const int n_out_vec = out_size / 4;       // 12.8M float4
    const int total_vec = n_src * DV;         // 25.6M float4 (fits int32)

    detect_idx_dtype_kernel<<<1, 1024>>>((const int*)idx, n_src);

    copy_kernel<<<(n_out_vec + 255) / 256, 256>>>(
        (const float4*)x, (float4*)out, n_out_vec);

    scatter_add_kernel<<<(total_vec + 255) / 256, 256>>>(
        idx, (const float4*)src, out, total_vec);
}

// round 2
// speedup vs baseline: 1.6705x; 1.6705x over previous
#include <cuda_runtime.h>
#include <cstdint>

// IndexAddInplace as a GATHER: out[j] = x[j] + sum_{i: idx[i]==j} src[i]
// x: [N_DST=100000, D=512] f32, idx: [N_SRC=200000] int64 (or int32, detected),
// src: [N_SRC, D] f32.
//
// Inverted index via atomicExch linked lists (no prefix sum needed):
//   next[i] = atomicExch(&head[idx[i]], i)
// Then one block per dst row walks its chain and accumulates in registers.
// Traffic: 205MB x-read + 410MB src-read + 205MB out-write (+~3MB index)
// vs copy+atomic-scatter's ~1.44GB. No atomics on the 205MB out region.

#define MAX_DST 100000
#define MAX_SRC 200000

__device__ int g_head[MAX_DST];
__device__ int g_next[MAX_SRC];
__device__ int g_any_odd_nonzero;   // 1 => idx is int32
__device__ int g_idx_is64;

// ---- 1. init: head = -1, clear detect flag ----
__global__ void init_kernel(int n_dst) {
    int t = blockIdx.x * blockDim.x + threadIdx.x;
    if (t == 0) g_any_odd_nonzero = 0;
    for (int j = t; j < n_dst; j += gridDim.x * blockDim.x)
        g_head[j] = -1;
}

// ---- 2. detect idx dtype (full-grid, ~0.8MB scan) ----
// If idx is int64 with values < 2^31, every odd 32-bit word is 0 (LE).
// If int32, odd words are random dst indices — some nonzero w/ certainty.
__global__ void detect_kernel(const int* __restrict__ idx32, int n_src) {
    int t = blockIdx.x * blockDim.x + threadIdx.x;
    int half = n_src >> 1;
    int local = 0;
    for (int i = t; i < half; i += gridDim.x * blockDim.x)
        if (idx32[2 * i + 1] != 0) local = 1;
    if (__syncthreads_or(local) && threadIdx.x == 0)
        atomicOr(&g_any_odd_nonzero, 1);
}

// ---- 3. build inverted index (linked lists) ----
__global__ void build_kernel(const void* __restrict__ idx_raw, int n_src) {
    if (blockIdx.x == 0 && threadIdx.x == 0)
        g_idx_is64 = g_any_odd_nonzero ? 0 : 1;   // harmless race: also computed locally below
    int is64 = !g_any_odd_nonzero;
    int t = blockIdx.x * blockDim.x + threadIdx.x;
    for (int i = t; i < n_src; i += gridDim.x * blockDim.x) {
        int d;
        if (is64) d = (int)((const long long*)idx_raw)[i];
        else      d = ((const int*)idx_raw)[i];
        g_next[i] = atomicExch(&g_head[d], i);
    }
}

// ---- 4. gather: one block per dst row, blockDim = D/4 threads ----
__global__ void gather_kernel(const float4* __restrict__ x,
                              const float4* __restrict__ src,
                              float4* __restrict__ out,
                              int dv) {
    int j = blockIdx.x;
    int c = threadIdx.x;
    size_t base = (size_t)j * dv + c;

    float4 acc = __ldcs(&x[base]);   // streaming: no reuse
    // chain walk: i is warp-uniform (broadcast loads on g_head/g_next)
    for (int i = __ldg(&g_head[j]); i >= 0; i = __ldg(&g_next[i])) {
        float4 v = __ldcs(&src[(size_t)i * dv + c]);
        acc.x += v.x; acc.y += v.y; acc.z += v.z; acc.w += v.w;
    }
    __stcs(&out[base], acc);
}

extern "C" void kernel_launch(void* const* d_in, const int* in_sizes, int n_in,
                              void* d_out, int out_size) {
    // Inputs: x [N_DST*D] f32, idx [N_SRC], src [N_SRC*D] f32
    const float* x   = (const float*)d_in[0];
    const void*  idx = (const void*)d_in[1];
    const float* src = (const float*)d_in[2];
    float* out = (float*)d_out;

    const int n_src = in_sizes[1];             // 200000
    const int d     = in_sizes[2] / n_src;     // 512
    const int n_dst = out_size / d;            // 100000
    const int dv    = d / 4;                   // 128 float4/row

    init_kernel<<<256, 256>>>(n_dst);
    detect_kernel<<<256, 256>>>((const int*)idx, n_src);
    build_kernel<<<256, 256>>>(idx, n_src);
    gather_kernel<<<n_dst, dv>>>((const float4*)x, (const float4*)src,
                                 (float4*)out, dv);
}

// round 3
// speedup vs baseline: 1.7102x; 1.0238x over previous
#include <cuda_runtime.h>
#include <cstdint>

// IndexAddInplace as a GATHER: out[j] = x[j] + sum_{i: idx[i]==j} src[i]
// x: [N_DST=100000, D=512] f32, idx: [N_SRC=200000] int64/int32 (detected),
// src: [N_SRC, D] f32.
//
// Inverted index: K inline slots per dst row (atomicAdd counter) + linked-list
// spill for the rare row with >K sources. Inline slots make the gather's src
// loads INDEPENDENT (no pointer-chase serialization) -> ~K x per-warp MLP.
// Traffic floor: 205MB x-read + 410MB src-read + 205MB out-write (+~4MB index).

#define MAX_DST 100000
#define MAX_SRC 200000
#define K_SLOTS 6

__device__ int g_cnt[MAX_DST];
__device__ int g_slot[MAX_DST * K_SLOTS];
__device__ int g_head[MAX_DST];            // spill chain heads
__device__ int g_next[MAX_SRC];            // spill chain links
__device__ int g_any_odd_nonzero = 0;      // 1 => idx is int32. Monotone 0->1 and
                                           // deterministic per dataset, so it never
                                           // needs clearing across graph replays.

// ---- 1. fused init (cnt=0, head=-1) + idx dtype detect ----
// int64 idx with values < 2^31 => every odd 32-bit word is 0 (LE).
// int32 idx => odd words are random dst indices, some nonzero w/ certainty.
__global__ void setup_kernel(const int* __restrict__ idx32, int n_src, int n_dst) {
    int t = blockIdx.x * blockDim.x + threadIdx.x;
    int stride = gridDim.x * blockDim.x;
    for (int j = t; j < n_dst; j += stride) {
        g_cnt[j] = 0;
        g_head[j] = -1;
    }
    int half = n_src >> 1;
    int local = 0;
    for (int i = t; i < half; i += stride)
        if (idx32[2 * i + 1] != 0) local = 1;
    if (__syncthreads_or(local) && threadIdx.x == 0)
        atomicOr(&g_any_odd_nonzero, 1);
}

// ---- 2. build inverted index: inline slots + spill chain ----
__global__ void build_kernel(const void* __restrict__ idx_raw, int n_src) {
    const int is64 = !g_any_odd_nonzero;
    int t = blockIdx.x * blockDim.x + threadIdx.x;
    int stride = gridDim.x * blockDim.x;
    for (int i = t; i < n_src; i += stride) {
        int d;
        if (is64) d = (int)((const long long*)idx_raw)[i];
        else      d = ((const int*)idx_raw)[i];
        int pos = atomicAdd(&g_cnt[d], 1);
        if (pos < K_SLOTS) g_slot[d * K_SLOTS + pos] = i;
        else               g_next[i] = atomicExch(&g_head[d], i);
    }
}

// ---- 3. gather: one block per dst row, blockDim = D/4 = 128 threads ----
__global__ void gather_kernel(const float4* __restrict__ x,
                              const float4* __restrict__ src,
                              float4* __restrict__ out,
                              int dv) {
    const int j = blockIdx.x;
    const int c = threadIdx.x;
    const size_t base = (size_t)j * dv + c;

    const int n = __ldg(&g_cnt[j]);               // warp-uniform, L2-resident
    const int m = n < K_SLOTS ? n : K_SLOTS;

    float4 acc = __ldcs(&x[base]);                // streaming: no reuse

    // Load slot indices first (warp-uniform, L2), then issue all src loads
    // independently — ptxas front-batches them (MLP = m).
    int ids[K_SLOTS];
    #pragma unroll
    for (int k = 0; k < K_SLOTS; k++)
        if (k < m) ids[k] = __ldg(&g_slot[j * K_SLOTS + k]);

    #pragma unroll
    for (int k = 0; k < K_SLOTS; k++) {
        if (k < m) {
            float4 v = __ldcs(&src[(size_t)ids[k] * dv + c]);
            acc.x += v.x; acc.y += v.y; acc.z += v.z; acc.w += v.w;
        }
    }

    // Rare spill (>K sources for this row): pointer-chase the remainder.
    if (n > K_SLOTS) {
        for (int i = __ldg(&g_head[j]); i >= 0; i = __ldg(&g_next[i])) {
            float4 v = __ldcs(&src[(size_t)i * dv + c]);
            acc.x += v.x; acc.y += v.y; acc.z += v.z; acc.w += v.w;
        }
    }

    __stcs(&out[base], acc);
}

extern "C" void kernel_launch(void* const* d_in, const int* in_sizes, int n_in,
                              void* d_out, int out_size) {
    // Inputs: x [N_DST*D] f32, idx [N_SRC], src [N_SRC*D] f32
    const float* x   = (const float*)d_in[0];
    const void*  idx = (const void*)d_in[1];
    const float* src = (const float*)d_in[2];
    float* out = (float*)d_out;

    const int n_src = in_sizes[1];             // 200000
    const int d     = in_sizes[2] / n_src;     // 512
    const int n_dst = out_size / d;            // 100000
    const int dv    = d / 4;                   // 128 float4/row

    setup_kernel<<<296, 256>>>((const int*)idx, n_src, n_dst);
    build_kernel<<<296, 256>>>(idx, n_src);
    gather_kernel<<<n_dst, dv>>>((const float4*)x, (const float4*)src,
                                 (float4*)out, dv);
}

// round 5
// speedup vs baseline: 1.7360x; 1.0151x over previous
#include <cuda_runtime.h>
#include <cstdint>

// IndexAddInplace as a GATHER: out[j] = x[j] + sum_{i: idx[i]==j} src[i]
// x: [N_DST=100000, D=512] f32, idx: [N_SRC=200000] int64/int32 (detected),
// src: [N_SRC, D] f32.
//
// Two kernels only:
//   build : K inline slots per dst row (atomicAdd counter) + linked-list spill
//           (encoded i+1, 0 = end, so zero-init IS the empty state).
//           idx dtype detected per-block from a shared 1024-word sample.
//   gather: one block per row; independent LDG.128s from the inline slots
//           (MLP ~= count), then — AFTER a __syncthreads() so every warp has
//           finished reading the per-row state — SELF-CLEANS cnt[j]/head[j]
//           so the next graph replay needs no init kernel.
//           (R4 failed 2.1e-3 rel_err because the clean raced warps 1-3's
//           initial g_cnt read; the barrier fixes it.)
// Traffic floor: 205MB x-read + 410MB src-read + 205MB out-write (+~4MB index).

#define MAX_DST 100000
#define MAX_SRC 200000
#define K_SLOTS 6
#define DETECT_WORDS 1024   // odd-word sample size for dtype detection

__device__ int g_cnt[MAX_DST];               // zero-init = empty
__device__ int g_slot[MAX_DST * K_SLOTS];
__device__ int g_head[MAX_DST];              // stores i+1; 0 = end (zero-init OK)
__device__ int g_next[MAX_SRC];              // stores i+1 links

// ---- 1. build inverted index (exact grid: one element per thread) ----
// Per-block dtype detect: int64 idx with values < 2^31 has ALL odd 32-bit
// words == 0 (LE); int32 idx has random dst indices there. Every block scans
// the same 1024-word sample (L2 broadcast) -> identical, deterministic answer.
__global__ void build_kernel(const void* __restrict__ idx_raw, int n_src) {
    const int* idx32 = (const int*)idx_raw;
    int local = 0;
    #pragma unroll
    for (int k = 0; k < DETECT_WORDS / 256; k++) {
        int w = threadIdx.x + k * 256;           // sample odd word w
        if (2 * w + 1 < n_src) local |= idx32[2 * w + 1];
    }
    const int is64 = !__syncthreads_or(local != 0);

    int i = blockIdx.x * blockDim.x + threadIdx.x;
    if (i >= n_src) return;

    int d;
    if (is64) d = (int)((const long long*)idx_raw)[i];
    else      d = idx32[i];

    int pos = atomicAdd(&g_cnt[d], 1);
    if (pos < K_SLOTS) g_slot[d * K_SLOTS + pos] = i;
    else               g_next[i] = atomicExch(&g_head[d], i + 1);
}

// ---- 2. gather: one block per dst row, blockDim = D/4 = 128 threads ----
__global__ void gather_kernel(const float4* __restrict__ x,
                              const float4* __restrict__ src,
                              float4* __restrict__ out,
                              int dv) {
    const int j = blockIdx.x;
    const int c = threadIdx.x;
    const size_t base = (size_t)j * dv + c;

    const int n = __ldg(&g_cnt[j]);              // warp-uniform, L2-resident
    const int m = n < K_SLOTS ? n : K_SLOTS;

    float4 acc = __ldcs(&x[base]);               // streaming: no reuse

    // Slot indices first (warp-uniform, L2), then all src loads issued
    // independently -> ptxas front-batches them (MLP = m).
    int ids[K_SLOTS];
    #pragma unroll
    for (int k = 0; k < K_SLOTS; k++)
        if (k < m) ids[k] = __ldg(&g_slot[j * K_SLOTS + k]);

    #pragma unroll
    for (int k = 0; k < K_SLOTS; k++) {
        if (k < m) {
            float4 v = __ldcs(&src[(size_t)ids[k] * dv + c]);
            acc.x += v.x; acc.y += v.y; acc.z += v.z; acc.w += v.w;
        }
    }

    // Rare spill (>K sources, ~0.45% of rows): walk the i+1-encoded chain.
    if (n > K_SLOTS) {
        for (int v1 = __ldg(&g_head[j]); v1 != 0; v1 = __ldg(&g_next[v1 - 1])) {
            float4 v = __ldcs(&src[(size_t)(v1 - 1) * dv + c]);
            acc.x += v.x; acc.y += v.y; acc.z += v.z; acc.w += v.w;
        }
    }

    __stcs(&out[base], acc);

    // All warps must have consumed this row's index state before we reset it.
    __syncthreads();

    // Self-clean this row's index state for the next graph replay.
    if (c == 0) {
        g_cnt[j] = 0;
        if (n > K_SLOTS) g_head[j] = 0;
    }
}

extern "C" void kernel_launch(void* const* d_in, const int* in_sizes, int n_in,
                              void* d_out, int out_size) {
    // Inputs: x [N_DST*D] f32, idx [N_SRC], src [N_SRC*D] f32
    const float* x   = (const float*)d_in[0];
    const void*  idx = (const void*)d_in[1];
    const float* src = (const float*)d_in[2];
    float* out = (float*)d_out;

    const int n_src = in_sizes[1];             // 200000
    const int d     = in_sizes[2] / n_src;     // 512
    const int n_dst = out_size / d;            // 100000
    const int dv    = d / 4;                   // 128 float4/row

    build_kernel<<<(n_src + 255) / 256, 256>>>(idx, n_src);
    gather_kernel<<<n_dst, dv>>>((const float4*)x, (const float4*)src,
                                 (float4*)out, dv);
}

// round 6
// speedup vs baseline: 1.7382x; 1.0013x over previous
#include <cuda_runtime.h>
#include <cstdint>

// IndexAddInplace as a GATHER: out[j] = x[j] + sum_{i: idx[i]==j} src[i]
// x: [N_DST=100000, D=512] f32, idx: [N_SRC=200000] int64/int32 (detected),
// src: [N_SRC, D] f32.
//
// build : K inline slots per dst row (atomicAdd counter) + linked-list spill
//         (encoded i+1, 0 = end, so zero-init IS the empty state).
//         idx dtype detected per-block from a shared 1024-word sample.
// gather: ONE WARP PER ROW (4 float4/lane). Per-row index state is private to
//         the warp, so the self-clean needs only __syncwarp() — removes the
//         block-wide BAR.SYNC tail that cost ~5us in the previous version.
//         4*(1+m) independent LDG.128s per warp (front-batched MLP).
// Traffic floor: 205MB x-read + 410MB src-read + 205MB out-write (+~4MB index).

#define MAX_DST 100000
#define MAX_SRC 200000
#define K_SLOTS 6
#define DETECT_WORDS 1024   // odd-word sample size for dtype detection

__device__ int g_cnt[MAX_DST];               // zero-init = empty
__device__ int g_slot[MAX_DST * K_SLOTS];
__device__ int g_head[MAX_DST];              // stores i+1; 0 = end (zero-init OK)
__device__ int g_next[MAX_SRC];              // stores i+1 links

// ---- 1. build inverted index (exact grid: one element per thread) ----
// Per-block dtype detect: int64 idx with values < 2^31 has ALL odd 32-bit
// words == 0 (LE); int32 idx has random dst indices there. Every block scans
// the same 1024-word sample (L2 broadcast) -> identical, deterministic answer.
__global__ void build_kernel(const void* __restrict__ idx_raw, int n_src) {
    const int* idx32 = (const int*)idx_raw;
    int local = 0;
    #pragma unroll
    for (int k = 0; k < DETECT_WORDS / 256; k++) {
        int w = threadIdx.x + k * 256;           // sample odd word w
        if (2 * w + 1 < n_src) local |= idx32[2 * w + 1];
    }
    const int is64 = !__syncthreads_or(local != 0);

    int i = blockIdx.x * blockDim.x + threadIdx.x;
    if (i >= n_src) return;

    int d;
    if (is64) d = (int)((const long long*)idx_raw)[i];
    else      d = idx32[i];

    int pos = atomicAdd(&g_cnt[d], 1);
    if (pos < K_SLOTS) g_slot[d * K_SLOTS + pos] = i;
    else               g_next[i] = atomicExch(&g_head[d], i + 1);
}

// ---- 2. gather: one WARP per dst row; lane handles cols c, c+32, c+64, c+96 ----
__global__ void __launch_bounds__(128)
gather_kernel(const float4* __restrict__ x,
              const float4* __restrict__ src,
              float4* __restrict__ out,
              int dv, int n_dst) {
    const int warp_id = (blockIdx.x * blockDim.x + threadIdx.x) >> 5;
    if (warp_id >= n_dst) return;
    const int j = warp_id;
    const int lane = threadIdx.x & 31;

    const int n = __ldg(&g_cnt[j]);              // warp-uniform, L2-resident
    const int m = n < K_SLOTS ? n : K_SLOTS;

    const size_t rbase = (size_t)j * dv + lane;  // dv = 128, 4 chunks of 32

    float4 acc[4];
    #pragma unroll
    for (int q = 0; q < 4; q++)
        acc[q] = __ldcs(&x[rbase + q * 32]);     // 4 independent streaming loads

    // Slot indices (warp-uniform, L2), then all 4*m src loads independent.
    int ids[K_SLOTS];
    #pragma unroll
    for (int k = 0; k < K_SLOTS; k++)
        if (k < m) ids[k] = __ldg(&g_slot[j * K_SLOTS + k]);

    #pragma unroll
    for (int k = 0; k < K_SLOTS; k++) {
        if (k < m) {
            const size_t sbase = (size_t)ids[k] * dv + lane;
            #pragma unroll
            for (int q = 0; q < 4; q++) {
                float4 v = __ldcs(&src[sbase + q * 32]);
                acc[q].x += v.x; acc[q].y += v.y;
                acc[q].z += v.z; acc[q].w += v.w;
            }
        }
    }

    // Rare spill (>K sources, ~0.45% of rows): walk the i+1-encoded chain.
    if (n > K_SLOTS) {
        for (int v1 = __ldg(&g_head[j]); v1 != 0; v1 = __ldg(&g_next[v1 - 1])) {
            const size_t sbase = (size_t)(v1 - 1) * dv + lane;
            #pragma unroll
            for (int q = 0; q < 4; q++) {
                float4 v = __ldcs(&src[sbase + q * 32]);
                acc[q].x += v.x; acc[q].y += v.y;
                acc[q].z += v.z; acc[q].w += v.w;
            }
        }
    }

    #pragma unroll
    for (int q = 0; q < 4; q++)
        __stcs(&out[rbase + q * 32], acc[q]);

    // Whole warp has consumed this row's state (all reads issued above).
    __syncwarp();
    if (lane == 0) {
        g_cnt[j] = 0;
        if (n > K_SLOTS) g_head[j] = 0;
    }
}

extern "C" void kernel_launch(void* const* d_in, const int* in_sizes, int n_in,
                              void* d_out, int out_size) {
    // Inputs: x [N_DST*D] f32, idx [N_SRC], src [N_SRC*D] f32
    const float* x   = (const float*)d_in[0];
    const void*  idx = (const void*)d_in[1];
    const float* src = (const float*)d_in[2];
    float* out = (float*)d_out;

    const int n_src = in_sizes[1];             // 200000
    const int d     = in_sizes[2] / n_src;     // 512
    const int n_dst = out_size / d;            // 100000
    const int dv    = d / 4;                   // 128 float4/row

    build_kernel<<<(n_src + 255) / 256, 256>>>(idx, n_src);

    const int rows_per_block = 128 / 32;       // 4 warps = 4 rows
    gather_kernel<<<(n_dst + rows_per_block - 1) / rows_per_block, 128>>>(
        (const float4*)x, (const float4*)src, (float4*)out, dv, n_dst);
}